// round 10
// baseline (speedup 1.0000x reference)
#include <cuda_runtime.h>

// CRPS loss, single fused kernel, float4-vectorized (4 pixels per thread):
//   term1 = mean_i |s_i - y|            per pixel
//   term2 = 0.5 * mean_{i,j} |s_i-s_j|  per pixel, via sorted-order identity:
//           sum_{i<j} |s_i - s_j| = sum_i (2i - 15) * v_sorted[i]   (N=16)
//   out   = mean over pixels of (sum1/16 - sum2/256)

#define NS     16
#define PIXELS (4 * 1 * 256 * 256)   // 262144
#define PIX4   (PIXELS / 4)          // 65536 float4 groups
#define TPB    256
#define NBLK   (PIX4 / TPB)          // 256 blocks

__device__ float        g_partial[NBLK];
__device__ unsigned int g_count;     // zero at load; last block resets each call

// Batcher odd-even mergesort, N=16: 63 compare-exchanges (FMNMX, alu pipe).
__device__ __forceinline__ void sort16(float v[NS])
{
#pragma unroll
    for (int p = 1; p < NS; p <<= 1) {
#pragma unroll
        for (int k = p; k >= 1; k >>= 1) {
#pragma unroll
            for (int j = k % p; j + k < NS; j += 2 * k) {
#pragma unroll
                for (int i = 0; i < k; ++i) {
                    if (i + j + k < NS) {
                        if ((i + j) / (2 * p) == (i + j + k) / (2 * p)) {
                            float a  = v[i + j];
                            float b  = v[i + j + k];
                            v[i + j]     = fminf(a, b);
                            v[i + j + k] = fmaxf(a, b);
                        }
                    }
                }
            }
        }
    }
}

// Per-pixel CRPS contribution from 16 register-resident samples + target.
__device__ __forceinline__ float crps_pixel(float v[NS], float y)
{
    float sum1 = 0.0f;
#pragma unroll
    for (int i = 0; i < NS; ++i)
        sum1 += fabsf(v[i] - y);

    sort16(v);

    float sum2 = 0.0f;
#pragma unroll
    for (int i = 0; i < NS; ++i)
        sum2 = fmaf((float)(2 * i - 15), v[i], sum2);

    return sum1 * (1.0f / 16.0f) - sum2 * (1.0f / 256.0f);
}

__global__ void __launch_bounds__(TPB) crps_fused_kernel(
    const float4* __restrict__ samples4,  // [16, PIX4]
    const float4* __restrict__ target4,   // [PIX4]
    float* __restrict__ out)
{
    const int tid = threadIdx.x;
    const int p4  = blockIdx.x * TPB + tid;          // exact fit, no guard

    // Front-batched independent 128-bit loads: 17 LDG.128 in flight.
    float4 v4[NS];
#pragma unroll
    for (int i = 0; i < NS; ++i)
        v4[i] = samples4[i * PIX4 + p4];
    const float4 y4 = target4[p4];

    // Split into four independent per-pixel streams (ILP for the alu pipe).
    float vx[NS], vy[NS], vz[NS], vw[NS];
#pragma unroll
    for (int i = 0; i < NS; ++i) {
        vx[i] = v4[i].x;  vy[i] = v4[i].y;
        vz[i] = v4[i].z;  vw[i] = v4[i].w;
    }

    float acc = crps_pixel(vx, y4.x);
    acc      += crps_pixel(vy, y4.y);
    acc      += crps_pixel(vz, y4.z);
    acc      += crps_pixel(vw, y4.w);

    // ── Block reduction: warp butterfly (fixed order -> deterministic) ──
#pragma unroll
    for (int m = 16; m >= 1; m >>= 1)
        acc += __shfl_xor_sync(0xFFFFFFFFu, acc, m);

    __shared__ float warp_sum[TPB / 32];             // 8 warps
    if ((tid & 31) == 0)
        warp_sum[tid >> 5] = acc;
    __syncthreads();

    __shared__ volatile int s_last;
    if (tid == 0) {
        float bsum = 0.0f;
#pragma unroll
        for (int w = 0; w < TPB / 32; ++w)
            bsum += warp_sum[w];
        g_partial[blockIdx.x] = bsum;
        __threadfence();                             // partial visible before count bump
        unsigned int prev = atomicAdd(&g_count, 1u);
        s_last = (prev == (unsigned int)(NBLK - 1)) ? 1 : 0;
    }
    __syncthreads();

    // ── Last block: deterministic final reduction over 256 partials ──
    if (s_last) {
        float a = __ldcg(&g_partial[tid]);           // L2-hot, one per thread

        __shared__ float sh[TPB];
        sh[tid] = a;
        __syncthreads();
#pragma unroll
        for (int s = TPB / 2; s > 0; s >>= 1) {
            if (tid < s) sh[tid] += sh[tid + s];
            __syncthreads();
        }
        if (tid == 0) {
            out[0] = sh[0] * (1.0f / (float)PIXELS);
            g_count = 0;                             // restore invariant for next replay
        }
    }
}

extern "C" void kernel_launch(void* const* d_in, const int* in_sizes, int n_in,
                              void* d_out, int out_size)
{
    const float* samples = (const float*)d_in[0];
    const float* target  = (const float*)d_in[1];
    // Robustness: samples has 16x the elements of target; fix ordering if flipped.
    if (n_in >= 2 && in_sizes[0] < in_sizes[1]) {
        const float* tmp = samples; samples = target; target = tmp;
    }

    crps_fused_kernel<<<NBLK, TPB>>>((const float4*)samples,
                                     (const float4*)target,
                                     (float*)d_out);
}

// round 13
// speedup vs baseline: 1.1050x; 1.1050x over previous
#include <cuda_runtime.h>

// CRPS loss, single fused kernel, float2-vectorized (2 pixels per thread):
//   term1 = mean_i |s_i - y|            per pixel
//   term2 = 0.5 * mean_{i,j} |s_i-s_j|  per pixel, via sorted-order identity:
//           sum_{i<j} |s_i - s_j| = sum_i (2i - 15) * v_sorted[i]   (N=16)
//   out   = mean over pixels of (sum1/16 - sum2/256)
//
// Register budget is the binding constraint (R10: 4 px/thread spilled at 118
// regs). 2 px/thread keeps live set ~60 regs: v2[16] (32) + one 16-float
// sort stream, processed sequentially per lane.

#define NS     16
#define PIXELS (4 * 1 * 256 * 256)   // 262144
#define PIX2   (PIXELS / 2)          // 131072 float2 groups
#define TPB    256
#define NBLK   (PIX2 / TPB)          // 512 blocks

__device__ float        g_partial[NBLK];
__device__ unsigned int g_count;     // zero at load; last block resets each call

// Batcher odd-even mergesort, N=16: 63 compare-exchanges (FMNMX, alu pipe).
__device__ __forceinline__ void sort16(float v[NS])
{
#pragma unroll
    for (int p = 1; p < NS; p <<= 1) {
#pragma unroll
        for (int k = p; k >= 1; k >>= 1) {
#pragma unroll
            for (int j = k % p; j + k < NS; j += 2 * k) {
#pragma unroll
                for (int i = 0; i < k; ++i) {
                    if (i + j + k < NS) {
                        if ((i + j) / (2 * p) == (i + j + k) / (2 * p)) {
                            float a  = v[i + j];
                            float b  = v[i + j + k];
                            v[i + j]     = fminf(a, b);
                            v[i + j + k] = fmaxf(a, b);
                        }
                    }
                }
            }
        }
    }
}

// Per-pixel CRPS contribution from 16 register-resident samples + target.
__device__ __forceinline__ float crps_pixel(float v[NS], float y)
{
    float sum1 = 0.0f;
#pragma unroll
    for (int i = 0; i < NS; ++i)
        sum1 += fabsf(v[i] - y);

    sort16(v);

    float sum2 = 0.0f;
#pragma unroll
    for (int i = 0; i < NS; ++i)
        sum2 = fmaf((float)(2 * i - 15), v[i], sum2);

    return sum1 * (1.0f / 16.0f) - sum2 * (1.0f / 256.0f);
}

__global__ void __launch_bounds__(TPB) crps_fused_kernel(
    const float2* __restrict__ samples2,  // [16, PIX2]
    const float2* __restrict__ target2,   // [PIX2]
    float* __restrict__ out)
{
    const int tid = threadIdx.x;
    const int p2  = blockIdx.x * TPB + tid;          // exact fit, no guard

    // Front-batched independent 64-bit loads: 17 LDG.64 in flight.
    float2 v2[NS];
#pragma unroll
    for (int i = 0; i < NS; ++i)
        v2[i] = samples2[i * PIX2 + p2];
    const float2 y2 = target2[p2];

    float acc;
    {   // pixel 0 (x lane) — scoped so its sort stream dies before lane y
        float v[NS];
#pragma unroll
        for (int i = 0; i < NS; ++i) v[i] = v2[i].x;
        acc = crps_pixel(v, y2.x);
    }
    {   // pixel 1 (y lane) — can consume v2[] in place
        float v[NS];
#pragma unroll
        for (int i = 0; i < NS; ++i) v[i] = v2[i].y;
        acc += crps_pixel(v, y2.y);
    }

    // ── Block reduction: warp butterfly (fixed order -> deterministic) ──
#pragma unroll
    for (int m = 16; m >= 1; m >>= 1)
        acc += __shfl_xor_sync(0xFFFFFFFFu, acc, m);

    __shared__ float warp_sum[TPB / 32];             // 8 warps
    if ((tid & 31) == 0)
        warp_sum[tid >> 5] = acc;
    __syncthreads();

    __shared__ volatile int s_last;
    if (tid == 0) {
        float bsum = 0.0f;
#pragma unroll
        for (int w = 0; w < TPB / 32; ++w)
            bsum += warp_sum[w];
        g_partial[blockIdx.x] = bsum;
        __threadfence();                             // partial visible before count bump
        unsigned int prev = atomicAdd(&g_count, 1u);
        s_last = (prev == (unsigned int)(NBLK - 1)) ? 1 : 0;
    }
    __syncthreads();

    // ── Last block: deterministic final reduction over 512 partials ──
    if (s_last) {
        float a = __ldcg(&g_partial[tid]) + __ldcg(&g_partial[tid + 256]);

        __shared__ float sh[TPB];
        sh[tid] = a;
        __syncthreads();
#pragma unroll
        for (int s = TPB / 2; s > 0; s >>= 1) {
            if (tid < s) sh[tid] += sh[tid + s];
            __syncthreads();
        }
        if (tid == 0) {
            out[0] = sh[0] * (1.0f / (float)PIXELS);
            g_count = 0;                             // restore invariant for next replay
        }
    }
}

extern "C" void kernel_launch(void* const* d_in, const int* in_sizes, int n_in,
                              void* d_out, int out_size)
{
    const float* samples = (const float*)d_in[0];
    const float* target  = (const float*)d_in[1];
    // Robustness: samples has 16x the elements of target; fix ordering if flipped.
    if (n_in >= 2 && in_sizes[0] < in_sizes[1]) {
        const float* tmp = samples; samples = target; target = tmp;
    }

    crps_fused_kernel<<<NBLK, TPB>>>((const float2*)samples,
                                     (const float2*)target,
                                     (float*)d_out);
}

// round 14
// speedup vs baseline: 2.0463x; 1.8519x over previous
#include <cuda_runtime.h>
#include <cuda_bf16.h>

// CRPS loss, single fused kernel, bf16x2-packed pixel pairs (2 px/thread):
//   term1 = mean_i |s_i - y|            per pixel (accumulated in exact f32)
//   term2 = 0.5 * mean_{i,j} |s_i-s_j|  per pixel, via sorted-order identity:
//           sum_{i<j} |s_i - s_j| = sum_i (2i - 15) * v_sorted[i]   (N=16)
//   out   = mean over pixels of (sum1/16 - sum2/256)
//
// Two pixels are packed into one __nv_bfloat162; the 63-CE Batcher network of
// __hmin2/__hmax2 sorts BOTH lanes at once. Data regs: 16 (vs 32+ f32), which
// is what killed the f32 2px/4px variants (spill -> L1 42%).

#define NS     16
#define PIXELS (4 * 1 * 256 * 256)   // 262144
#define PIX2   (PIXELS / 2)          // 131072 pixel pairs
#define TPB    256
#define NBLK   (PIX2 / TPB)          // 512 blocks

__device__ float        g_partial[NBLK];
__device__ unsigned int g_count;     // zero at load; last block resets each call

__device__ __forceinline__ void ce2(__nv_bfloat162& a, __nv_bfloat162& b)
{
    __nv_bfloat162 lo = __hmin2(a, b);
    __nv_bfloat162 hi = __hmax2(a, b);
    a = lo;
    b = hi;
}

__global__ void __launch_bounds__(TPB) crps_fused_kernel(
    const float2* __restrict__ samples2,  // [16, PIX2]
    const float2* __restrict__ target2,   // [PIX2]
    float* __restrict__ out)
{
    const int tid = threadIdx.x;
    const int p2  = blockIdx.x * TPB + tid;          // exact fit, no guard

    const float2 y2 = target2[p2];

    // Stream loads: each float2 feeds exact-f32 term1, then is packed to
    // bf16x2 and dies. Live set: v[16] bf16x2 = 16 regs + accumulators.
    __nv_bfloat162 v[NS];
    float s1x = 0.0f, s1y = 0.0f;
#pragma unroll
    for (int i = 0; i < NS; ++i) {
        float2 s = samples2[i * PIX2 + p2];
        s1x += fabsf(s.x - y2.x);
        s1y += fabsf(s.y - y2.y);
        v[i] = __floats2bfloat162_rn(s.x, s.y);      // lo = pixel x, hi = pixel y
    }

    // Batcher odd-even mergesort, N=16: 63 packed compare-exchanges
    // (HMNMX2) sorting both bf16 lanes independently.
#pragma unroll
    for (int p = 1; p < NS; p <<= 1) {
#pragma unroll
        for (int k = p; k >= 1; k >>= 1) {
#pragma unroll
            for (int j = k % p; j + k < NS; j += 2 * k) {
#pragma unroll
                for (int i = 0; i < k; ++i) {
                    if (i + j + k < NS) {
                        if ((i + j) / (2 * p) == (i + j + k) / (2 * p))
                            ce2(v[i + j], v[i + j + k]);
                    }
                }
            }
        }
    }

    // sum_{i<j}(v_j - v_i) via sorted weights, f32 accumulation per lane.
    float s2x = 0.0f, s2y = 0.0f;
#pragma unroll
    for (int i = 0; i < NS; ++i) {
        const float w = (float)(2 * i - 15);
        s2x = fmaf(w, __low2float(v[i]),  s2x);
        s2y = fmaf(w, __high2float(v[i]), s2y);
    }

    float acc = (s1x + s1y) * (1.0f / 16.0f) - (s2x + s2y) * (1.0f / 256.0f);

    // ── Block reduction: warp butterfly (fixed order -> deterministic) ──
#pragma unroll
    for (int m = 16; m >= 1; m >>= 1)
        acc += __shfl_xor_sync(0xFFFFFFFFu, acc, m);

    __shared__ float warp_sum[TPB / 32];             // 8 warps
    if ((tid & 31) == 0)
        warp_sum[tid >> 5] = acc;
    __syncthreads();

    __shared__ volatile int s_last;
    if (tid == 0) {
        float bsum = 0.0f;
#pragma unroll
        for (int w = 0; w < TPB / 32; ++w)
            bsum += warp_sum[w];
        g_partial[blockIdx.x] = bsum;
        __threadfence();                             // partial visible before count bump
        unsigned int prev = atomicAdd(&g_count, 1u);
        s_last = (prev == (unsigned int)(NBLK - 1)) ? 1 : 0;
    }
    __syncthreads();

    // ── Last block: deterministic final reduction over 512 partials ──
    if (s_last) {
        float a = __ldcg(&g_partial[tid]) + __ldcg(&g_partial[tid + 256]);

        __shared__ float sh[TPB];
        sh[tid] = a;
        __syncthreads();
#pragma unroll
        for (int s = TPB / 2; s > 0; s >>= 1) {
            if (tid < s) sh[tid] += sh[tid + s];
            __syncthreads();
        }
        if (tid == 0) {
            out[0] = sh[0] * (1.0f / (float)PIXELS);
            g_count = 0;                             // restore invariant for next replay
        }
    }
}

extern "C" void kernel_launch(void* const* d_in, const int* in_sizes, int n_in,
                              void* d_out, int out_size)
{
    const float* samples = (const float*)d_in[0];
    const float* target  = (const float*)d_in[1];
    // Robustness: samples has 16x the elements of target; fix ordering if flipped.
    if (n_in >= 2 && in_sizes[0] < in_sizes[1]) {
        const float* tmp = samples; samples = target; target = tmp;
    }

    crps_fused_kernel<<<NBLK, TPB>>>((const float2*)samples,
                                     (const float2*)target,
                                     (float*)d_out);
}